// round 8
// baseline (speedup 1.0000x reference)
#include <cuda_runtime.h>
#include <cuda_fp16.h>

// 2-layer GCN, N=100000, E=3200000, 25->16->2, log_softmax.
// out_l[i] = dinv[i]*(sum_{j->i} g[j] + g[i]) + b,  g = dinv * (x @ W).
// CSR-by-target per call (deg -> hierarchical scan -> fill); aggregations are
// pure gathers (fp32 accumulation), fused epilogues. Layer-1 payload fp16.
// gather1: 4 lanes/node (feature-half x neighbor-parity). gather2: 2 lanes.
// edge_index is int32 on device.

#define NMAX   100000
#define EMAX   3200000
#define F_IN   25
#define F_HID  16
#define F_OUT  2
#define SB     1024

struct __align__(16) H8 { __half2 h[4]; };   // 8 halfs = 16B

// ---- scratch (device globals; no allocation allowed) ----
__device__ int   d_deg [NMAX];
__device__ int   d_ptr [NMAX];
__device__ int   d_pos [NMAX];
__device__ int   d_bsum[128];
__device__ int   d_src [EMAX];
__device__ float d_dinv[NMAX];
__device__ H8    d_g1h [NMAX * 2];       // 16 halfs per node (32B)
__device__ float d_g2  [NMAX * F_OUT];

// ---- kernels ----

__global__ void k_zero(int n) {
    int i = blockIdx.x * blockDim.x + threadIdx.x;
    if (i < n) d_deg[i] = 0;
}

// 4 edges per thread (int4 when aligned).
__global__ void k_deg(const int* __restrict__ col, int n_edges, int n_nodes) {
    int i = blockIdx.x * blockDim.x + threadIdx.x;
    int base = i * 4;
    if (base >= n_edges) return;
    if (base + 3 < n_edges) {
        int4 v = __ldg(reinterpret_cast<const int4*>(col + base));
        unsigned t0 = (unsigned)v.x, t1 = (unsigned)v.y;
        unsigned t2 = (unsigned)v.z, t3 = (unsigned)v.w;
        if (t0 < (unsigned)n_nodes) atomicAdd(&d_deg[t0], 1);
        if (t1 < (unsigned)n_nodes) atomicAdd(&d_deg[t1], 1);
        if (t2 < (unsigned)n_nodes) atomicAdd(&d_deg[t2], 1);
        if (t3 < (unsigned)n_nodes) atomicAdd(&d_deg[t3], 1);
    } else {
        for (int e = base; e < n_edges; e++) {
            unsigned t = (unsigned)__ldg(&col[e]);
            if (t < (unsigned)n_nodes) atomicAdd(&d_deg[t], 1);
        }
    }
}

// Scan stage 1: per-block exclusive scan, block total out.
__global__ void k_scan1(int n) {
    __shared__ int s[SB];
    int t = threadIdx.x;
    int i = blockIdx.x * SB + t;
    int v = (i < n) ? d_deg[i] : 0;
    s[t] = v;
    __syncthreads();
#pragma unroll
    for (int off = 1; off < SB; off <<= 1) {
        int u = (t >= off) ? s[t - off] : 0;
        __syncthreads();
        if (t >= off) s[t] += u;
        __syncthreads();
    }
    if (i < n) d_ptr[i] = s[t] - v;
    if (t == SB - 1) d_bsum[blockIdx.x] = s[t];
}

// Scan stage 2: single block scans the (<=128) block totals.
__global__ void k_scan2(int nb) {
    __shared__ int s[128];
    int t = threadIdx.x;
    int v = (t < nb) ? d_bsum[t] : 0;
    s[t] = v;
    __syncthreads();
#pragma unroll
    for (int off = 1; off < 128; off <<= 1) {
        int u = (t >= off) ? s[t - off] : 0;
        __syncthreads();
        if (t >= off) s[t] += u;
        __syncthreads();
    }
    if (t < nb) d_bsum[t] = s[t] - v;
}

// Scan stage 3: add block offset; finalize ptr, seed fill cursors.
__global__ void k_scan3(int n) {
    int i = blockIdx.x * SB + threadIdx.x;
    if (i >= n) return;
    int val = d_ptr[i] + d_bsum[blockIdx.x];
    d_ptr[i] = val;
    d_pos[i] = val;
}

// Fill CSR, 4 edges per thread.
__global__ void k_fill(const int* __restrict__ row,
                       const int* __restrict__ col, int n_edges, int n_nodes) {
    int i = blockIdx.x * blockDim.x + threadIdx.x;
    int base = i * 4;
    if (base >= n_edges) return;
    if (base + 3 < n_edges) {
        int4 rv = __ldg(reinterpret_cast<const int4*>(row + base));
        int4 tv = __ldg(reinterpret_cast<const int4*>(col + base));
        int rr[4] = {rv.x, rv.y, rv.z, rv.w};
        int tt[4] = {tv.x, tv.y, tv.z, tv.w};
#pragma unroll
        for (int q = 0; q < 4; q++) {
            unsigned r = (unsigned)rr[q], t = (unsigned)tt[q];
            if (r < (unsigned)n_nodes && t < (unsigned)n_nodes) {
                int slot = atomicAdd(&d_pos[t], 1);
                d_src[slot] = (int)r;
            }
        }
    } else {
        for (int e = base; e < n_edges; e++) {
            unsigned r = (unsigned)__ldg(&row[e]);
            unsigned t = (unsigned)__ldg(&col[e]);
            if (r < (unsigned)n_nodes && t < (unsigned)n_nodes) {
                int slot = atomicAdd(&d_pos[t], 1);
                d_src[slot] = (int)r;
            }
        }
    }
}

// dinv = rsqrt(deg_in + 1);  g1 = dinv * (x @ W1), stored fp16-packed.
__global__ void k_node1(const float* __restrict__ x,
                        const float* __restrict__ W1, int n) {
    __shared__ float sW[F_IN * F_HID];
    for (int i = threadIdx.x; i < F_IN * F_HID; i += blockDim.x)
        sW[i] = W1[i];
    __syncthreads();

    int i = blockIdx.x * blockDim.x + threadIdx.x;
    if (i >= n) return;

    float xv[F_IN];
#pragma unroll
    for (int k = 0; k < F_IN; k++) xv[k] = x[i * F_IN + k];

    float dinv = rsqrtf((float)(d_deg[i] + 1));
    d_dinv[i] = dinv;

    float s[F_HID];
#pragma unroll
    for (int f = 0; f < F_HID; f++) {
        float acc = 0.0f;
#pragma unroll
        for (int k = 0; k < F_IN; k++) acc += xv[k] * sW[k * F_HID + f];
        s[f] = dinv * acc;
    }
#pragma unroll
    for (int c = 0; c < 2; c++) {
        H8 o;
#pragma unroll
        for (int k = 0; k < 4; k++)
            o.h[k] = __floats2half2_rn(s[c * 8 + 2 * k], s[c * 8 + 2 * k + 1]);
        d_g1h[i * 2 + c] = o;
    }
}

// Gather layer 1 + epilogue-1 + layer-2 transform, fused.
// 4 lanes/node: c = (neighbor parity)<<1 | (feature half).
// Lane pair (2p, 2p+1) loads neighbor j's two 16B halves -> one 32B sector.
__global__ void k_gather1(const float* __restrict__ b1,
                          const float* __restrict__ W2, int n) {
    int gid = blockIdx.x * blockDim.x + threadIdx.x;
    int i = gid >> 2;
    int c = gid & 3;
    int half = c >> 1;     // neighbor parity
    int part = c & 1;      // feature half
    bool valid = (i < n);
    int ic = valid ? i : (n - 1);   // clamp: keep quad active for shfl

    int start = d_ptr[ic];
    int deg = d_deg[ic];
    float dinv = d_dinv[ic];

    float a[8];
#pragma unroll
    for (int q = 0; q < 8; q++) a[q] = 0.0f;

    int k = half;
    for (; k + 6 < deg; k += 8) {
        int j0 = __ldg(&d_src[start + k + 0]);
        int j1 = __ldg(&d_src[start + k + 2]);
        int j2 = __ldg(&d_src[start + k + 4]);
        int j3 = __ldg(&d_src[start + k + 6]);
        H8 v0 = d_g1h[j0 * 2 + part];
        H8 v1 = d_g1h[j1 * 2 + part];
        H8 v2 = d_g1h[j2 * 2 + part];
        H8 v3 = d_g1h[j3 * 2 + part];
#pragma unroll
        for (int q = 0; q < 4; q++) {
            float2 f0 = __half22float2(v0.h[q]);
            float2 f1 = __half22float2(v1.h[q]);
            float2 f2 = __half22float2(v2.h[q]);
            float2 f3 = __half22float2(v3.h[q]);
            a[2 * q]     += (f0.x + f1.x) + (f2.x + f3.x);
            a[2 * q + 1] += (f0.y + f1.y) + (f2.y + f3.y);
        }
    }
    for (; k < deg; k += 2) {
        int j = __ldg(&d_src[start + k]);
        H8 v = d_g1h[j * 2 + part];
#pragma unroll
        for (int q = 0; q < 4; q++) {
            float2 f = __half22float2(v.h[q]);
            a[2 * q] += f.x; a[2 * q + 1] += f.y;
        }
    }

    // merge neighbor parities (lanes differ in bit 1)
#pragma unroll
    for (int q = 0; q < 8; q++)
        a[q] += __shfl_xor_sync(0xffffffffu, a[q], 2);

    // add self term for this feature half
    {
        H8 v = d_g1h[ic * 2 + part];
#pragma unroll
        for (int q = 0; q < 4; q++) {
            float2 f = __half22float2(v.h[q]);
            a[2 * q] += f.x; a[2 * q + 1] += f.y;
        }
    }

    // epilogue-1: relu(dinv*a + b1), partial dot into W2
    float h0 = 0.0f, h1 = 0.0f;
#pragma unroll
    for (int f = 0; f < 8; f++) {
        int fg = part * 8 + f;
        float tt = fmaxf(dinv * a[f] + __ldg(&b1[fg]), 0.0f);
        h0 += tt * __ldg(&W2[fg * F_OUT + 0]);
        h1 += tt * __ldg(&W2[fg * F_OUT + 1]);
    }
    // merge feature halves (lanes differ in bit 0)
    h0 += __shfl_xor_sync(0xffffffffu, h0, 1);
    h1 += __shfl_xor_sync(0xffffffffu, h1, 1);

    if (valid && c == 0) {
        d_g2[i * 2 + 0] = dinv * h0;
        d_g2[i * 2 + 1] = dinv * h1;
    }
}

// Gather layer 2 + epilogue-2 + log_softmax, fused. 2 lanes/node.
__global__ void k_gather2(const float* __restrict__ b2,
                          float* __restrict__ out, int n) {
    int gid = blockIdx.x * blockDim.x + threadIdx.x;
    int i = gid >> 1;
    int c = gid & 1;
    bool valid = (i < n);
    int ic = valid ? i : (n - 1);

    int start = d_ptr[ic];
    int deg = d_deg[ic];
    float dinv = d_dinv[ic];

    float2 acc = make_float2(0.0f, 0.0f);

    int k = c;
    for (; k + 6 < deg; k += 8) {
        int j0 = __ldg(&d_src[start + k + 0]);
        int j1 = __ldg(&d_src[start + k + 2]);
        int j2 = __ldg(&d_src[start + k + 4]);
        int j3 = __ldg(&d_src[start + k + 6]);
        float2 v0 = *reinterpret_cast<const float2*>(&d_g2[j0 * 2]);
        float2 v1 = *reinterpret_cast<const float2*>(&d_g2[j1 * 2]);
        float2 v2 = *reinterpret_cast<const float2*>(&d_g2[j2 * 2]);
        float2 v3 = *reinterpret_cast<const float2*>(&d_g2[j3 * 2]);
        acc.x += (v0.x + v1.x) + (v2.x + v3.x);
        acc.y += (v0.y + v1.y) + (v2.y + v3.y);
    }
    for (; k < deg; k += 2) {
        int j = __ldg(&d_src[start + k]);
        float2 v = *reinterpret_cast<const float2*>(&d_g2[j * 2]);
        acc.x += v.x; acc.y += v.y;
    }

    // merge parities (lanes differ in bit 0)
    acc.x += __shfl_xor_sync(0xffffffffu, acc.x, 1);
    acc.y += __shfl_xor_sync(0xffffffffu, acc.y, 1);

    if (valid && c == 0) {
        float2 g = *reinterpret_cast<const float2*>(&d_g2[i * 2]);  // self
        float z0 = dinv * (acc.x + g.x) + __ldg(&b2[0]);
        float z1 = dinv * (acc.y + g.y) + __ldg(&b2[1]);
        float m = fmaxf(z0, z1);
        float lse = m + logf(expf(z0 - m) + expf(z1 - m));
        out[i * 2 + 0] = z0 - lse;
        out[i * 2 + 1] = z1 - lse;
    }
}

// ---- launch ----

extern "C" void kernel_launch(void* const* d_in, const int* in_sizes, int n_in,
                              void* d_out, int out_size) {
    const float* x  = (const float*)d_in[0];
    const int*   ei = (const int*)d_in[1];
    const float* W1 = (const float*)d_in[2];
    const float* b1 = (const float*)d_in[3];
    const float* W2 = (const float*)d_in[4];
    const float* b2 = (const float*)d_in[5];
    float*       out = (float*)d_out;

    int n_nodes = in_sizes[0] / F_IN;
    int n_edges = in_sizes[1] / 2;
    const int* row = ei;             // sources
    const int* col = ei + n_edges;   // targets

    const int B = 256;
    int gn  = (n_nodes + B - 1) / B;
    int ge4 = (int)(((n_edges + 3) / 4 + B - 1) / B);
    int gn2 = (int)((2LL * n_nodes + B - 1) / B);
    int gn4 = (int)((4LL * n_nodes + B - 1) / B);
    int nb  = (n_nodes + SB - 1) / SB;

    k_zero   <<<gn, B>>>(n_nodes);
    k_deg    <<<ge4, B>>>(col, n_edges, n_nodes);
    k_node1  <<<gn, B>>>(x, W1, n_nodes);
    k_scan1  <<<nb, SB>>>(n_nodes);
    k_scan2  <<<1, 128>>>(nb);
    k_scan3  <<<nb, SB>>>(n_nodes);
    k_fill   <<<ge4, B>>>(row, col, n_edges, n_nodes);
    k_gather1<<<gn4, B>>>(b1, W2, n_nodes);
    k_gather2<<<gn2, B>>>(b2, out, n_nodes);
}

// round 9
// speedup vs baseline: 1.2181x; 1.2181x over previous
#include <cuda_runtime.h>
#include <cuda_fp16.h>

// 2-layer GCN, N=100000, E=3200000, 25->16->2, log_softmax.
// out_l[i] = dinv[i]*(sum_{j->i} g[j] + g[i]) + b,  g = dinv * (x @ W).
// CSR-by-target built per call (deg -> hierarchical scan -> fill); both
// aggregation layers are pure gathers (fp32 accumulation), fused epilogues.
// Layer-1 payload stored fp16 (32B/node) to halve random-gather traffic.
// gather1: 2 lanes/node (R7 layout — lane pair coalesces to one 32B sector),
// inner unroll deepened to 8 neighbors for more MLP.
// edge_index is int32 on device.

#define NMAX   100000
#define EMAX   3200000
#define F_IN   25
#define F_HID  16
#define F_OUT  2
#define SB     1024

struct __align__(16) H8 { __half2 h[4]; };   // 8 halfs = 16B

// ---- scratch (device globals; no allocation allowed) ----
__device__ int   d_deg [NMAX];
__device__ int   d_ptr [NMAX];
__device__ int   d_pos [NMAX];
__device__ int   d_bsum[128];
__device__ int   d_src [EMAX];
__device__ float d_dinv[NMAX];
__device__ H8    d_g1h [NMAX * 2];       // 16 halfs per node (32B)
__device__ float d_g2  [NMAX * F_OUT];

// ---- kernels ----

__global__ void k_zero(int n) {
    int i = blockIdx.x * blockDim.x + threadIdx.x;
    if (i < n) d_deg[i] = 0;
}

__global__ void k_deg(const int* __restrict__ col, int n_edges, int n_nodes) {
    int i = blockIdx.x * blockDim.x + threadIdx.x;
    if (i >= n_edges) return;
    unsigned t = (unsigned)__ldg(&col[i]);
    if (t < (unsigned)n_nodes) atomicAdd(&d_deg[t], 1);
}

// Scan stage 1: per-block exclusive scan (1 element/thread), block total out.
__global__ void k_scan1(int n) {
    __shared__ int s[SB];
    int t = threadIdx.x;
    int i = blockIdx.x * SB + t;
    int v = (i < n) ? d_deg[i] : 0;
    s[t] = v;
    __syncthreads();
#pragma unroll
    for (int off = 1; off < SB; off <<= 1) {
        int u = (t >= off) ? s[t - off] : 0;
        __syncthreads();
        if (t >= off) s[t] += u;
        __syncthreads();
    }
    if (i < n) d_ptr[i] = s[t] - v;
    if (t == SB - 1) d_bsum[blockIdx.x] = s[t];
}

// Scan stage 2: single block scans the (<=128) block totals.
__global__ void k_scan2(int nb) {
    __shared__ int s[128];
    int t = threadIdx.x;
    int v = (t < nb) ? d_bsum[t] : 0;
    s[t] = v;
    __syncthreads();
#pragma unroll
    for (int off = 1; off < 128; off <<= 1) {
        int u = (t >= off) ? s[t - off] : 0;
        __syncthreads();
        if (t >= off) s[t] += u;
        __syncthreads();
    }
    if (t < nb) d_bsum[t] = s[t] - v;
}

// Scan stage 3: add block offset; finalize ptr, seed fill cursors.
__global__ void k_scan3(int n) {
    int i = blockIdx.x * SB + threadIdx.x;
    if (i >= n) return;
    int val = d_ptr[i] + d_bsum[blockIdx.x];
    d_ptr[i] = val;
    d_pos[i] = val;
}

// Fill CSR: slot = pos[target]++, src[slot] = source.
__global__ void k_fill(const int* __restrict__ row,
                       const int* __restrict__ col, int n_edges, int n_nodes) {
    int e = blockIdx.x * blockDim.x + threadIdx.x;
    if (e >= n_edges) return;
    unsigned r = (unsigned)__ldg(&row[e]);
    unsigned t = (unsigned)__ldg(&col[e]);
    if (r >= (unsigned)n_nodes || t >= (unsigned)n_nodes) return;
    int slot = atomicAdd(&d_pos[t], 1);
    d_src[slot] = (int)r;
}

// dinv = rsqrt(deg_in + 1);  g1 = dinv * (x @ W1), stored fp16-packed.
__global__ void k_node1(const float* __restrict__ x,
                        const float* __restrict__ W1, int n) {
    __shared__ float sW[F_IN * F_HID];
    for (int i = threadIdx.x; i < F_IN * F_HID; i += blockDim.x)
        sW[i] = W1[i];
    __syncthreads();

    int i = blockIdx.x * blockDim.x + threadIdx.x;
    if (i >= n) return;

    float xv[F_IN];
#pragma unroll
    for (int k = 0; k < F_IN; k++) xv[k] = x[i * F_IN + k];

    float dinv = rsqrtf((float)(d_deg[i] + 1));
    d_dinv[i] = dinv;

    float s[F_HID];
#pragma unroll
    for (int f = 0; f < F_HID; f++) {
        float acc = 0.0f;
#pragma unroll
        for (int k = 0; k < F_IN; k++) acc += xv[k] * sW[k * F_HID + f];
        s[f] = dinv * acc;
    }
#pragma unroll
    for (int c = 0; c < 2; c++) {
        H8 o;
#pragma unroll
        for (int k = 0; k < 4; k++)
            o.h[k] = __floats2half2_rn(s[c * 8 + 2 * k], s[c * 8 + 2 * k + 1]);
        d_g1h[i * 2 + c] = o;
    }
}

// Gather layer 1 + epilogue-1 + layer-2 transform, fused.
// 2 lanes per node; lane c owns features [8c, 8c+8). The lane pair's two 16B
// loads of a neighbor coalesce into one 32B sector. fp32 accumulation.
// Inner unroll = 8 neighbors in flight.
__global__ void k_gather1(const float* __restrict__ b1,
                          const float* __restrict__ W2, int n) {
    int gid = blockIdx.x * blockDim.x + threadIdx.x;
    int i = gid >> 1;
    int c = gid & 1;
    bool valid = (i < n);
    int ic = valid ? i : (n - 1);   // clamp: keep lane pair active for shfl

    int start = d_ptr[ic];
    int deg = d_deg[ic];
    float dinv = d_dinv[ic];

    float a[8];
    {
        H8 v = d_g1h[ic * 2 + c];    // self term
#pragma unroll
        for (int k = 0; k < 4; k++) {
            float2 f = __half22float2(v.h[k]);
            a[2 * k] = f.x; a[2 * k + 1] = f.y;
        }
    }

    int k = 0;
    for (; k + 8 <= deg; k += 8) {
        int jj[8];
#pragma unroll
        for (int q = 0; q < 8; q++) jj[q] = __ldg(&d_src[start + k + q]);
        H8 vv[8];
#pragma unroll
        for (int q = 0; q < 8; q++) vv[q] = d_g1h[jj[q] * 2 + c];
#pragma unroll
        for (int q = 0; q < 8; q++) {
#pragma unroll
            for (int p = 0; p < 4; p++) {
                float2 f = __half22float2(vv[q].h[p]);
                a[2 * p] += f.x; a[2 * p + 1] += f.y;
            }
        }
    }
    for (; k < deg; k++) {
        int j = __ldg(&d_src[start + k]);
        H8 v = d_g1h[j * 2 + c];
#pragma unroll
        for (int q = 0; q < 4; q++) {
            float2 f = __half22float2(v.h[q]);
            a[2 * q] += f.x; a[2 * q + 1] += f.y;
        }
    }

    // epilogue-1: relu(dinv*a + b1), partial dot into W2
    float h0 = 0.0f, h1 = 0.0f;
#pragma unroll
    for (int f = 0; f < 8; f++) {
        int fg = c * 8 + f;
        float tt = fmaxf(dinv * a[f] + __ldg(&b1[fg]), 0.0f);
        h0 += tt * __ldg(&W2[fg * F_OUT + 0]);
        h1 += tt * __ldg(&W2[fg * F_OUT + 1]);
    }
    h0 += __shfl_xor_sync(0xffffffffu, h0, 1);
    h1 += __shfl_xor_sync(0xffffffffu, h1, 1);

    if (valid && c == 0) {
        d_g2[i * 2 + 0] = dinv * h0;
        d_g2[i * 2 + 1] = dinv * h1;
    }
}

// Gather layer 2 + epilogue-2 + log_softmax, fused. 1 thread per node.
__global__ void k_gather2(const float* __restrict__ b2,
                          float* __restrict__ out, int n) {
    int i = blockIdx.x * blockDim.x + threadIdx.x;
    if (i >= n) return;

    int start = d_ptr[i];
    int deg = d_deg[i];
    float dinv = d_dinv[i];

    float2 acc = *reinterpret_cast<const float2*>(&d_g2[i * 2]);

    int k = 0;
    for (; k + 8 <= deg; k += 8) {
        int jj[8];
#pragma unroll
        for (int q = 0; q < 8; q++) jj[q] = __ldg(&d_src[start + k + q]);
#pragma unroll
        for (int q = 0; q < 8; q++) {
            float2 v = *reinterpret_cast<const float2*>(&d_g2[jj[q] * 2]);
            acc.x += v.x; acc.y += v.y;
        }
    }
    for (; k < deg; k++) {
        int j = __ldg(&d_src[start + k]);
        float2 v = *reinterpret_cast<const float2*>(&d_g2[j * 2]);
        acc.x += v.x; acc.y += v.y;
    }

    float z0 = dinv * acc.x + __ldg(&b2[0]);
    float z1 = dinv * acc.y + __ldg(&b2[1]);
    float m = fmaxf(z0, z1);
    float lse = m + logf(expf(z0 - m) + expf(z1 - m));
    out[i * 2 + 0] = z0 - lse;
    out[i * 2 + 1] = z1 - lse;
}

// ---- launch ----

extern "C" void kernel_launch(void* const* d_in, const int* in_sizes, int n_in,
                              void* d_out, int out_size) {
    const float* x  = (const float*)d_in[0];
    const int*   ei = (const int*)d_in[1];
    const float* W1 = (const float*)d_in[2];
    const float* b1 = (const float*)d_in[3];
    const float* W2 = (const float*)d_in[4];
    const float* b2 = (const float*)d_in[5];
    float*       out = (float*)d_out;

    int n_nodes = in_sizes[0] / F_IN;
    int n_edges = in_sizes[1] / 2;
    const int* row = ei;             // sources
    const int* col = ei + n_edges;   // targets

    const int B = 256;
    int gn  = (n_nodes + B - 1) / B;
    int ge  = (n_edges + B - 1) / B;
    int gn2 = (int)((2LL * n_nodes + B - 1) / B);
    int nb  = (n_nodes + SB - 1) / SB;

    k_zero   <<<gn, B>>>(n_nodes);
    k_deg    <<<ge, B>>>(col, n_edges, n_nodes);
    k_node1  <<<gn, B>>>(x, W1, n_nodes);
    k_scan1  <<<nb, SB>>>(n_nodes);
    k_scan2  <<<1, 128>>>(nb);
    k_scan3  <<<nb, SB>>>(n_nodes);
    k_fill   <<<ge, B>>>(row, col, n_edges, n_nodes);
    k_gather1<<<gn2, B>>>(b1, W2, n_nodes);
    k_gather2<<<gn, B>>>(b2, out, n_nodes);
}

// round 10
// speedup vs baseline: 1.5251x; 1.2521x over previous
#include <cuda_runtime.h>
#include <cuda_fp16.h>

// 2-layer GCN, N=100000, E=3200000, 25->16->2, log_softmax.
// out_l[i] = dinv[i]*(sum_{j->i} g[j] + g[i]) + b,  g = dinv * (x @ W).
// Bucketed CSR: fixed CAP slots per target node -> fill needs NO prefix scan
// and doubles as the degree pass. Overflow (P ~ 1e-50 at CAP=128) spills to a
// small list scanned only by affected nodes (exactness preserved).
// Gathers: fp32 accumulation, fused epilogues; layer-1 payload fp16 (32B).
// edge_index is int32 on device.

#define NMAX   100000
#define CAP    128
#define F_IN   25
#define F_HID  16
#define F_OUT  2
#define SPILLMAX 8192

struct __align__(16) H8 { __half2 h[4]; };   // 8 halfs = 16B

// ---- scratch (device globals; no allocation allowed) ----
__device__ int   d_cnt [NMAX];            // degree counters (= deg after fill)
__device__ int   d_srcb[NMAX * CAP];      // bucketed CSR: sources per target
__device__ int   d_spill_n;
__device__ int   d_spill[2 * SPILLMAX];   // (target, source) overflow pairs
__device__ float d_dinv[NMAX];
__device__ H8    d_g1h [NMAX * 2];        // 16 halfs per node (32B)
__device__ float d_g2  [NMAX * F_OUT];

// ---- kernels ----

__global__ void k_zero(int n) {
    int i = blockIdx.x * blockDim.x + threadIdx.x;
    if (i < n) d_cnt[i] = 0;
    if (i == 0) d_spill_n = 0;
}

// Fill bucketed CSR; counters double as degree histogram.
__global__ void k_fill(const int* __restrict__ row,
                       const int* __restrict__ col, int n_edges, int n_nodes) {
    int e = blockIdx.x * blockDim.x + threadIdx.x;
    if (e >= n_edges) return;
    unsigned r = (unsigned)__ldg(&row[e]);
    unsigned t = (unsigned)__ldg(&col[e]);
    if (r >= (unsigned)n_nodes || t >= (unsigned)n_nodes) return;
    int slot = atomicAdd(&d_cnt[t], 1);
    if (slot < CAP) {
        d_srcb[t * CAP + slot] = (int)r;
    } else {
        int s = atomicAdd(&d_spill_n, 1);
        if (s < SPILLMAX) {
            d_spill[2 * s + 0] = (int)t;
            d_spill[2 * s + 1] = (int)r;
        }
    }
}

// dinv = rsqrt(deg_in + 1);  g1 = dinv * (x @ W1), stored fp16-packed.
__global__ void k_node1(const float* __restrict__ x,
                        const float* __restrict__ W1, int n) {
    __shared__ float sW[F_IN * F_HID];
    for (int i = threadIdx.x; i < F_IN * F_HID; i += blockDim.x)
        sW[i] = W1[i];
    __syncthreads();

    int i = blockIdx.x * blockDim.x + threadIdx.x;
    if (i >= n) return;

    float xv[F_IN];
#pragma unroll
    for (int k = 0; k < F_IN; k++) xv[k] = x[i * F_IN + k];

    float dinv = rsqrtf((float)(d_cnt[i] + 1));
    d_dinv[i] = dinv;

    float s[F_HID];
#pragma unroll
    for (int f = 0; f < F_HID; f++) {
        float acc = 0.0f;
#pragma unroll
        for (int k = 0; k < F_IN; k++) acc += xv[k] * sW[k * F_HID + f];
        s[f] = dinv * acc;
    }
#pragma unroll
    for (int c = 0; c < 2; c++) {
        H8 o;
#pragma unroll
        for (int k = 0; k < 4; k++)
            o.h[k] = __floats2half2_rn(s[c * 8 + 2 * k], s[c * 8 + 2 * k + 1]);
        d_g1h[i * 2 + c] = o;
    }
}

// Gather layer 1 + epilogue-1 + layer-2 transform, fused.
// 2 lanes per node; lane c owns features [8c, 8c+8). The lane pair's two 16B
// loads of a neighbor coalesce into one 32B sector. fp32 accumulation.
__global__ void k_gather1(const float* __restrict__ b1,
                          const float* __restrict__ W2, int n) {
    int gid = blockIdx.x * blockDim.x + threadIdx.x;
    int i = gid >> 1;
    int c = gid & 1;
    bool valid = (i < n);
    int ic = valid ? i : (n - 1);   // clamp: keep lane pair active for shfl

    int cnt = d_cnt[ic];
    int deg = min(cnt, CAP);
    int base = ic * CAP;
    float dinv = d_dinv[ic];

    float a[8];
    {
        H8 v = d_g1h[ic * 2 + c];    // self term
#pragma unroll
        for (int k = 0; k < 4; k++) {
            float2 f = __half22float2(v.h[k]);
            a[2 * k] = f.x; a[2 * k + 1] = f.y;
        }
    }

    int k = 0;
    for (; k + 4 <= deg; k += 4) {
        int j0 = __ldg(&d_srcb[base + k + 0]);
        int j1 = __ldg(&d_srcb[base + k + 1]);
        int j2 = __ldg(&d_srcb[base + k + 2]);
        int j3 = __ldg(&d_srcb[base + k + 3]);
        H8 v0 = d_g1h[j0 * 2 + c];
        H8 v1 = d_g1h[j1 * 2 + c];
        H8 v2 = d_g1h[j2 * 2 + c];
        H8 v3 = d_g1h[j3 * 2 + c];
#pragma unroll
        for (int q = 0; q < 4; q++) {
            float2 f0 = __half22float2(v0.h[q]);
            float2 f1 = __half22float2(v1.h[q]);
            float2 f2 = __half22float2(v2.h[q]);
            float2 f3 = __half22float2(v3.h[q]);
            a[2 * q]     += (f0.x + f1.x) + (f2.x + f3.x);
            a[2 * q + 1] += (f0.y + f1.y) + (f2.y + f3.y);
        }
    }
    for (; k < deg; k++) {
        int j = __ldg(&d_srcb[base + k]);
        H8 v = d_g1h[j * 2 + c];
#pragma unroll
        for (int q = 0; q < 4; q++) {
            float2 f = __half22float2(v.h[q]);
            a[2 * q] += f.x; a[2 * q + 1] += f.y;
        }
    }

    // overflow path (expected never taken): scan spill list for this target
    if (cnt > CAP) {
        int ns = min(d_spill_n, SPILLMAX);
        for (int s = 0; s < ns; s++) {
            if (d_spill[2 * s] == ic) {
                int j = d_spill[2 * s + 1];
                H8 v = d_g1h[j * 2 + c];
#pragma unroll
                for (int q = 0; q < 4; q++) {
                    float2 f = __half22float2(v.h[q]);
                    a[2 * q] += f.x; a[2 * q + 1] += f.y;
                }
            }
        }
    }

    // epilogue-1: relu(dinv*a + b1), partial dot into W2
    float h0 = 0.0f, h1 = 0.0f;
#pragma unroll
    for (int f = 0; f < 8; f++) {
        int fg = c * 8 + f;
        float tt = fmaxf(dinv * a[f] + __ldg(&b1[fg]), 0.0f);
        h0 += tt * __ldg(&W2[fg * F_OUT + 0]);
        h1 += tt * __ldg(&W2[fg * F_OUT + 1]);
    }
    h0 += __shfl_xor_sync(0xffffffffu, h0, 1);
    h1 += __shfl_xor_sync(0xffffffffu, h1, 1);

    if (valid && c == 0) {
        d_g2[i * 2 + 0] = dinv * h0;
        d_g2[i * 2 + 1] = dinv * h1;
    }
}

// Gather layer 2 + epilogue-2 + log_softmax, fused. 1 thread per node.
__global__ void k_gather2(const float* __restrict__ b2,
                          float* __restrict__ out, int n) {
    int i = blockIdx.x * blockDim.x + threadIdx.x;
    if (i >= n) return;

    int cnt = d_cnt[i];
    int deg = min(cnt, CAP);
    int base = i * CAP;
    float dinv = d_dinv[i];

    float2 acc = *reinterpret_cast<const float2*>(&d_g2[i * 2]);

    int k = 0;
    for (; k + 8 <= deg; k += 8) {
        int jj[8];
#pragma unroll
        for (int q = 0; q < 8; q++) jj[q] = __ldg(&d_srcb[base + k + q]);
#pragma unroll
        for (int q = 0; q < 8; q++) {
            float2 v = *reinterpret_cast<const float2*>(&d_g2[jj[q] * 2]);
            acc.x += v.x; acc.y += v.y;
        }
    }
    for (; k < deg; k++) {
        int j = __ldg(&d_srcb[base + k]);
        float2 v = *reinterpret_cast<const float2*>(&d_g2[j * 2]);
        acc.x += v.x; acc.y += v.y;
    }

    if (cnt > CAP) {
        int ns = min(d_spill_n, SPILLMAX);
        for (int s = 0; s < ns; s++) {
            if (d_spill[2 * s] == i) {
                int j = d_spill[2 * s + 1];
                float2 v = *reinterpret_cast<const float2*>(&d_g2[j * 2]);
                acc.x += v.x; acc.y += v.y;
            }
        }
    }

    float z0 = dinv * acc.x + __ldg(&b2[0]);
    float z1 = dinv * acc.y + __ldg(&b2[1]);
    float m = fmaxf(z0, z1);
    float lse = m + logf(expf(z0 - m) + expf(z1 - m));
    out[i * 2 + 0] = z0 - lse;
    out[i * 2 + 1] = z1 - lse;
}

// ---- launch ----

extern "C" void kernel_launch(void* const* d_in, const int* in_sizes, int n_in,
                              void* d_out, int out_size) {
    const float* x  = (const float*)d_in[0];
    const int*   ei = (const int*)d_in[1];
    const float* W1 = (const float*)d_in[2];
    const float* b1 = (const float*)d_in[3];
    const float* W2 = (const float*)d_in[4];
    const float* b2 = (const float*)d_in[5];
    float*       out = (float*)d_out;

    int n_nodes = in_sizes[0] / F_IN;
    int n_edges = in_sizes[1] / 2;
    const int* row = ei;             // sources
    const int* col = ei + n_edges;   // targets

    const int B = 256;
    int gn  = (n_nodes + B - 1) / B;
    int ge  = (n_edges + B - 1) / B;
    int gn2 = (int)((2LL * n_nodes + B - 1) / B);

    k_zero   <<<gn, B>>>(n_nodes);
    k_fill   <<<ge, B>>>(row, col, n_edges, n_nodes);
    k_node1  <<<gn, B>>>(x, W1, n_nodes);
    k_gather1<<<gn2, B>>>(b1, W2, n_nodes);
    k_gather2<<<gn, B>>>(b2, out, n_nodes);
}